// round 7
// baseline (speedup 1.0000x reference)
#include <cuda_runtime.h>

// Fresh-written every call (deterministic; reset by last block).
__device__ double g_plogp_partial[2048];
__device__ double g_seg_partial[256];
__device__ int    g_done_count = 0;

#define NT     512
#define NBLK   1184              /* 148 SMs x 4 blocks x 2 waves */
#define LN2_D  0.69314718055994530942

// blocks [0, B)     : per-row segment reduce, then EXIT (off critical path;
//                     wave-2 stream blocks backfill their SM slots)
// blocks [B, NBLK)  : barrier-free streaming p*log2(p) over pred
// last block to finish: sums all partials, writes the scalar.
__global__ void __launch_bounds__(NT, 4)
fused_kernel(const float* __restrict__ pred, long long n4,
             const float* __restrict__ action_probs,
             const float* __restrict__ value,
             const float* __restrict__ critic_value,
             const int*   __restrict__ segments,
             int B, int nPlogp,
             float* __restrict__ out, double inv_BL) {
    __shared__ float sh_ws[16];
    __shared__ bool  sh_is_last;

    const int t    = threadIdx.x;
    const int lane = t & 31;
    const int wid  = t >> 5;

    if (blockIdx.x < (unsigned)B) {
        // ---------------- segment path (tiny, exits early) ----------------
        __shared__ float sh_logp[512];
        __shared__ int   sh_seg[512];      // staged: coalesced global loads
        __shared__ short sh_segid[512];
        __shared__ float sh_segsum[513];
        __shared__ int   sh_nseg;

        const int L = 512;
        const int row = blockIdx.x;
        const long long base = (long long)row * L;

        sh_logp[t] = __logf(action_probs[base + t]);
        sh_seg[t]  = segments[base + t];
        __syncthreads();

        if (t == 0) {
            float acc = 0.0f;
            int cnt = 0;
            for (int l = 0; l < L; l++) {
                sh_segid[l] = (short)cnt;
                acc += sh_logp[l];
                if (sh_seg[l] != 0) {
                    sh_segsum[cnt] = acc;
                    acc = 0.0f;
                    cnt++;
                }
            }
            sh_segsum[cnt] = acc;   // trailing tail segment
            sh_nseg = cnt;
        }
        __syncthreads();

        float slp = sh_segsum[sh_segid[t]];
        // Faithful reference quirk: tail of the LAST batch row stays zero.
        if (row == B - 1 && (int)sh_segid[t] == sh_nseg) slp = 0.0f;

        float adv  = value[base + t] - critic_value[base + t];
        float term = fmaf(adv, 0.5f * adv, -adv * slp);

        #pragma unroll
        for (int o = 16; o > 0; o >>= 1)
            term += __shfl_down_sync(0xffffffffu, term, o);
        if (lane == 0) sh_ws[wid] = term;
        __syncthreads();
        if (t == 0) {
            double blk = 0.0;
            #pragma unroll
            for (int i = 0; i < 16; i++) blk += (double)sh_ws[i];
            g_seg_partial[row] = blk;
        }
    } else {
        // ---------------- plogp: barrier-free HBM stream -------------------
        const int bid = blockIdx.x - B;
        const float4* __restrict__ p4 = reinterpret_cast<const float4*>(pred);

        const long long stride = (long long)nPlogp * NT;
        long long idx = (long long)bid * NT + t;

        float s0 = 0.0f, s1 = 0.0f, s2 = 0.0f, s3 = 0.0f;

        // 4 independent streaming LDG.128 in flight (MLP_p1 = 4).
        while (idx + 3 * stride < n4) {
            float4 a = __ldcs(&p4[idx]);
            float4 b = __ldcs(&p4[idx + stride]);
            float4 c = __ldcs(&p4[idx + 2 * stride]);
            float4 d = __ldcs(&p4[idx + 3 * stride]);

            s0 = fmaf(a.x, __log2f(a.x), s0);
            s0 = fmaf(a.y, __log2f(a.y), s0);
            s0 = fmaf(a.z, __log2f(a.z), s0);
            s0 = fmaf(a.w, __log2f(a.w), s0);
            s1 = fmaf(b.x, __log2f(b.x), s1);
            s1 = fmaf(b.y, __log2f(b.y), s1);
            s1 = fmaf(b.z, __log2f(b.z), s1);
            s1 = fmaf(b.w, __log2f(b.w), s1);
            s2 = fmaf(c.x, __log2f(c.x), s2);
            s2 = fmaf(c.y, __log2f(c.y), s2);
            s2 = fmaf(c.z, __log2f(c.z), s2);
            s2 = fmaf(c.w, __log2f(c.w), s2);
            s3 = fmaf(d.x, __log2f(d.x), s3);
            s3 = fmaf(d.y, __log2f(d.y), s3);
            s3 = fmaf(d.z, __log2f(d.z), s3);
            s3 = fmaf(d.w, __log2f(d.w), s3);

            idx += 4 * stride;
        }
        // Paired remainder (MLP-2 for the leftover stride-steps).
        if (idx + stride < n4) {
            float4 a = __ldcs(&p4[idx]);
            float4 b = __ldcs(&p4[idx + stride]);
            s0 = fmaf(a.x, __log2f(a.x), s0);
            s0 = fmaf(a.y, __log2f(a.y), s0);
            s0 = fmaf(a.z, __log2f(a.z), s0);
            s0 = fmaf(a.w, __log2f(a.w), s0);
            s1 = fmaf(b.x, __log2f(b.x), s1);
            s1 = fmaf(b.y, __log2f(b.y), s1);
            s1 = fmaf(b.z, __log2f(b.z), s1);
            s1 = fmaf(b.w, __log2f(b.w), s1);
            idx += 2 * stride;
        }
        if (idx < n4) {
            float4 a = __ldcs(&p4[idx]);
            s2 = fmaf(a.x, __log2f(a.x), s2);
            s2 = fmaf(a.y, __log2f(a.y), s2);
            s2 = fmaf(a.z, __log2f(a.z), s2);
            s2 = fmaf(a.w, __log2f(a.w), s2);
        }

        float s = (s0 + s1) + (s2 + s3);   // stays in log2 domain

        #pragma unroll
        for (int o = 16; o > 0; o >>= 1)
            s += __shfl_down_sync(0xffffffffu, s, o);
        if (lane == 0) sh_ws[wid] = s;
        __syncthreads();
        if (t == 0) {
            double blk = 0.0;
            #pragma unroll
            for (int i = 0; i < 16; i++) blk += (double)sh_ws[i];
            g_plogp_partial[bid] = blk;
        }
    }

    // ---------------- last-block finalize -----------------------------------
    if (t == 0) {
        __threadfence();
        int prev = atomicAdd(&g_done_count, 1);
        sh_is_last = (prev == NBLK - 1);
    }
    __syncthreads();
    if (!sh_is_last) return;

    __shared__ double sh_d[16];
    double v = 0.0;
    for (int i = t; i < nPlogp; i += NT) v += g_plogp_partial[i];
    v *= (0.005 * LN2_D);                     // log2 -> ln + entropy coef
    for (int i = t; i < B; i += NT) v += g_seg_partial[i];

    #pragma unroll
    for (int o = 16; o > 0; o >>= 1)
        v += __shfl_down_sync(0xffffffffu, v, o);
    if (lane == 0) sh_d[wid] = v;
    __syncthreads();
    if (t == 0) {
        double tot = 0.0;
        #pragma unroll
        for (int i = 0; i < 16; i++) tot += sh_d[i];
        out[0] = (float)(tot * inv_BL);
        g_done_count = 0;                     // reset for graph replay
    }
}

extern "C" void kernel_launch(void* const* d_in, const int* in_sizes, int n_in,
                              void* d_out, int out_size) {
    const float* pred         = (const float*)d_in[0];
    const float* action_probs = (const float*)d_in[1];
    const float* value        = (const float*)d_in[2];
    const float* critic_value = (const float*)d_in[3];
    const int*   segments     = (const int*)d_in[4];

    const long long n_pred = in_sizes[0];   // B*L*V (divisible by 4)
    const int BL = in_sizes[1];             // B*L
    const int B = BL / 512;

    float* out = (float*)d_out;

    const int nPlogp = NBLK - B;            // 1168 streaming blocks

    fused_kernel<<<NBLK, NT>>>(pred, n_pred >> 2,
                               action_probs, value, critic_value,
                               segments, B, nPlogp,
                               out, 1.0 / (double)BL);
}

// round 8
// speedup vs baseline: 1.0107x; 1.0107x over previous
#include <cuda_runtime.h>

// Fresh-written every call (deterministic; reset by last block).
__device__ double g_plogp_partial[2048];
__device__ double g_seg_partial[256];
__device__ int    g_done_count = 0;

#define NT     512
#define NBLK   1184              /* 148 SMs x 4 blocks x 2 waves */
#define LN2_D  0.69314718055994530942

// blocks [0, B)     : per-row segment reduce, then EXIT (off critical path;
//                     wave-2 stream blocks backfill their SM slots)
// blocks [B, NBLK)  : barrier-free streaming p*log2(p) over pred
// last block to finish: sums all partials, writes the scalar.
__global__ void __launch_bounds__(NT, 4)
fused_kernel(const float* __restrict__ pred, long long n4,
             const float* __restrict__ action_probs,
             const float* __restrict__ value,
             const float* __restrict__ critic_value,
             const int*   __restrict__ segments,
             int B, int nPlogp,
             float* __restrict__ out, double inv_BL) {
    __shared__ float sh_ws[16];
    __shared__ bool  sh_is_last;

    const int t    = threadIdx.x;
    const int lane = t & 31;
    const int wid  = t >> 5;

    if (blockIdx.x < (unsigned)B) {
        // ---------------- segment path (tiny, exits early) ----------------
        __shared__ float sh_logp[512];
        __shared__ int   sh_seg[512];      // staged: coalesced global loads
        __shared__ short sh_segid[512];
        __shared__ float sh_segsum[513];
        __shared__ int   sh_nseg;

        const int L = 512;
        const int row = blockIdx.x;
        const long long base = (long long)row * L;

        sh_logp[t] = __logf(action_probs[base + t]);
        sh_seg[t]  = segments[base + t];
        __syncthreads();

        if (t == 0) {
            float acc = 0.0f;
            int cnt = 0;
            for (int l = 0; l < L; l++) {
                sh_segid[l] = (short)cnt;
                acc += sh_logp[l];
                if (sh_seg[l] != 0) {
                    sh_segsum[cnt] = acc;
                    acc = 0.0f;
                    cnt++;
                }
            }
            sh_segsum[cnt] = acc;   // trailing tail segment
            sh_nseg = cnt;
        }
        __syncthreads();

        float slp = sh_segsum[sh_segid[t]];
        // Faithful reference quirk: tail of the LAST batch row stays zero.
        if (row == B - 1 && (int)sh_segid[t] == sh_nseg) slp = 0.0f;

        float adv  = value[base + t] - critic_value[base + t];
        float term = fmaf(adv, 0.5f * adv, -adv * slp);

        #pragma unroll
        for (int o = 16; o > 0; o >>= 1)
            term += __shfl_down_sync(0xffffffffu, term, o);
        if (lane == 0) sh_ws[wid] = term;
        __syncthreads();
        if (t == 0) {
            double blk = 0.0;
            #pragma unroll
            for (int i = 0; i < 16; i++) blk += (double)sh_ws[i];
            g_seg_partial[row] = blk;
        }
    } else {
        // ---------------- plogp: barrier-free HBM stream -------------------
        const int bid = blockIdx.x - B;
        const float4* __restrict__ p4 = reinterpret_cast<const float4*>(pred);

        const long long stride = (long long)nPlogp * NT;
        long long idx = (long long)bid * NT + t;

        float s0 = 0.0f, s1 = 0.0f, s2 = 0.0f, s3 = 0.0f;

        // 4 independent streaming LDG.128 in flight (MLP_p1 = 4).
        while (idx + 3 * stride < n4) {
            float4 a = __ldcs(&p4[idx]);
            float4 b = __ldcs(&p4[idx + stride]);
            float4 c = __ldcs(&p4[idx + 2 * stride]);
            float4 d = __ldcs(&p4[idx + 3 * stride]);

            s0 = fmaf(a.x, __log2f(a.x), s0);
            s0 = fmaf(a.y, __log2f(a.y), s0);
            s0 = fmaf(a.z, __log2f(a.z), s0);
            s0 = fmaf(a.w, __log2f(a.w), s0);
            s1 = fmaf(b.x, __log2f(b.x), s1);
            s1 = fmaf(b.y, __log2f(b.y), s1);
            s1 = fmaf(b.z, __log2f(b.z), s1);
            s1 = fmaf(b.w, __log2f(b.w), s1);
            s2 = fmaf(c.x, __log2f(c.x), s2);
            s2 = fmaf(c.y, __log2f(c.y), s2);
            s2 = fmaf(c.z, __log2f(c.z), s2);
            s2 = fmaf(c.w, __log2f(c.w), s2);
            s3 = fmaf(d.x, __log2f(d.x), s3);
            s3 = fmaf(d.y, __log2f(d.y), s3);
            s3 = fmaf(d.z, __log2f(d.z), s3);
            s3 = fmaf(d.w, __log2f(d.w), s3);

            idx += 4 * stride;
        }
        // Paired remainder (MLP-2 for the leftover stride-steps).
        if (idx + stride < n4) {
            float4 a = __ldcs(&p4[idx]);
            float4 b = __ldcs(&p4[idx + stride]);
            s0 = fmaf(a.x, __log2f(a.x), s0);
            s0 = fmaf(a.y, __log2f(a.y), s0);
            s0 = fmaf(a.z, __log2f(a.z), s0);
            s0 = fmaf(a.w, __log2f(a.w), s0);
            s1 = fmaf(b.x, __log2f(b.x), s1);
            s1 = fmaf(b.y, __log2f(b.y), s1);
            s1 = fmaf(b.z, __log2f(b.z), s1);
            s1 = fmaf(b.w, __log2f(b.w), s1);
            idx += 2 * stride;
        }
        if (idx < n4) {
            float4 a = __ldcs(&p4[idx]);
            s2 = fmaf(a.x, __log2f(a.x), s2);
            s2 = fmaf(a.y, __log2f(a.y), s2);
            s2 = fmaf(a.z, __log2f(a.z), s2);
            s2 = fmaf(a.w, __log2f(a.w), s2);
        }

        float s = (s0 + s1) + (s2 + s3);   // stays in log2 domain

        #pragma unroll
        for (int o = 16; o > 0; o >>= 1)
            s += __shfl_down_sync(0xffffffffu, s, o);
        if (lane == 0) sh_ws[wid] = s;
        __syncthreads();
        if (t == 0) {
            double blk = 0.0;
            #pragma unroll
            for (int i = 0; i < 16; i++) blk += (double)sh_ws[i];
            g_plogp_partial[bid] = blk;
        }
    }

    // ---------------- last-block finalize -----------------------------------
    if (t == 0) {
        __threadfence();
        int prev = atomicAdd(&g_done_count, 1);
        sh_is_last = (prev == NBLK - 1);
    }
    __syncthreads();
    if (!sh_is_last) return;

    __shared__ double sh_d[16];
    double v = 0.0;
    for (int i = t; i < nPlogp; i += NT) v += g_plogp_partial[i];
    v *= (0.005 * LN2_D);                     // log2 -> ln + entropy coef
    for (int i = t; i < B; i += NT) v += g_seg_partial[i];

    #pragma unroll
    for (int o = 16; o > 0; o >>= 1)
        v += __shfl_down_sync(0xffffffffu, v, o);
    if (lane == 0) sh_d[wid] = v;
    __syncthreads();
    if (t == 0) {
        double tot = 0.0;
        #pragma unroll
        for (int i = 0; i < 16; i++) tot += sh_d[i];
        out[0] = (float)(tot * inv_BL);
        g_done_count = 0;                     // reset for graph replay
    }
}

extern "C" void kernel_launch(void* const* d_in, const int* in_sizes, int n_in,
                              void* d_out, int out_size) {
    const float* pred         = (const float*)d_in[0];
    const float* action_probs = (const float*)d_in[1];
    const float* value        = (const float*)d_in[2];
    const float* critic_value = (const float*)d_in[3];
    const int*   segments     = (const int*)d_in[4];

    const long long n_pred = in_sizes[0];   // B*L*V (divisible by 4)
    const int BL = in_sizes[1];             // B*L
    const int B = BL / 512;

    float* out = (float*)d_out;

    const int nPlogp = NBLK - B;            // 1168 streaming blocks

    fused_kernel<<<NBLK, NT>>>(pred, n_pred >> 2,
                               action_probs, value, critic_value,
                               segments, B, nPlogp,
                               out, 1.0 / (double)BL);
}